// round 7
// baseline (speedup 1.0000x reference)
#include <cuda_runtime.h>
#include <cuda_bf16.h>
#include <math.h>

// Problem constants
#define L_SEQ   2048
#define NB      128      // batch
#define HID     512
#define EMB     256
#define KTOT    768      // HID + EMB
#define NCTA    64       // 2 M-tiles x 32 N-slices
#define NTHR    128      // 4 warps
#define KCH     64       // K chunk staged per inner iteration (12 chunks)
#define SW      772      // W smem row stride (floats), 772%32==4 -> conflict-free frags
#define SA      68       // A/G smem row stride (floats), 68%32==4

// Scratch (device globals: allocation-free rule)
__device__ float    g_H[2][NB][HID];                         // 512 KB ping-pong H
__device__ float    g_Xe[(size_t)L_SEQ * NB * EMB];          // 256 MB gathered embeddings (tf32-rounded)
__device__ unsigned g_bar;                                   // grid barrier counter (monotonic per launch)

// smem bytes: W(64x772) + A/G(64x68) + C(64x16) + bias(64)
#define SMEM_BYTES ((64*SW + 64*SA + 64*16 + 64) * 4)

__device__ __forceinline__ float tf32r(float x) {
    unsigned u;
    asm("cvt.rna.tf32.f32 %0, %1;" : "=r"(u) : "f"(x));
    return __uint_as_float(u);
}
__device__ __forceinline__ float sigf(float x) {
    return 1.f / (1.f + __expf(-x));
}
__device__ __forceinline__ float tanhfast(float x) {
    x = fminf(fmaxf(x, -15.f), 15.f);
    float e = __expf(2.f * x);
    return (e - 1.f) / (e + 1.f);
}

__device__ __forceinline__ void mma_tf32(float* d, const unsigned* a, const unsigned* b) {
    asm volatile(
        "mma.sync.aligned.m16n8k8.row.col.f32.tf32.tf32.f32 "
        "{%0,%1,%2,%3}, {%4,%5,%6,%7}, {%8,%9}, {%0,%1,%2,%3};"
        : "+f"(d[0]), "+f"(d[1]), "+f"(d[2]), "+f"(d[3])
        : "r"(a[0]), "r"(a[1]), "r"(a[2]), "r"(a[3]), "r"(b[0]), "r"(b[1]));
}

// ---------------- init: reset barrier + zero H[0] ----------------
__global__ void lstm_init() {
    int i = blockIdx.x * blockDim.x + threadIdx.x;
    if (i == 0) g_bar = 0u;
    if (i < NB * HID) ((float*)g_H)[i] = 0.f;   // zero H buffer 0
}

// ---------------- gather: Xe[t][n][:] = tf32(E[X[n][t]]) ----------------
__global__ void lstm_gather(const int* __restrict__ X, const float* __restrict__ E) {
    int row  = blockIdx.x * 8 + (threadIdx.x >> 5);   // row = t*128 + n, 262144 rows
    int lane = threadIdx.x & 31;
    int n = row & (NB - 1);
    int t = row >> 7;
    int v = X[n * L_SEQ + t];
    const float4* src = (const float4*)(E + (size_t)v * EMB);
    float4* dst = (float4*)(g_Xe + (size_t)row * EMB);
    float4 a = src[lane];
    a.x = tf32r(a.x); a.y = tf32r(a.y); a.z = tf32r(a.z); a.w = tf32r(a.w);
    dst[lane] = a;
    float4 b = src[lane + 32];
    b.x = tf32r(b.x); b.y = tf32r(b.y); b.z = tf32r(b.z); b.w = tf32r(b.w);
    dst[lane + 32] = b;
}

// ---------------- persistent recurrent kernel ----------------
__global__ void __launch_bounds__(NTHR, 1)
lstm_rec(const float* __restrict__ Ww, const float* __restrict__ Wb, float* __restrict__ out) {
    extern __shared__ float sm[];
    float* Ws = sm;                       // [64][772]
    float* As = sm + 64 * SW;             // [64][68]  (A chunk staging, reused as G)
    float* Cs = As + 64 * SA;             // [64][16]  cell state
    float* Bs = Cs + 64 * 16;             // [64]      biases

    const int tid = threadIdx.x;
    const int cm  = blockIdx.x & 1;       // M tile: rows cm*64 .. +64
    const int cn  = blockIdx.x >> 1;      // N slice: hidden units cn*16 .. +16

    // Load W slice (tf32-rounded) and bias. Local col n: gate g=n/16, unit u=n%16,
    // global W row = g*512 + cn*16 + u.
    for (int n = 0; n < 64; ++n) {
        int grow = (n >> 4) * HID + cn * 16 + (n & 15);
        const float* src = Ww + (size_t)grow * KTOT;
        for (int k = tid; k < KTOT; k += NTHR) Ws[n * SW + k] = tf32r(src[k]);
    }
    if (tid < 64) {
        int grow = (tid >> 4) * HID + cn * 16 + (tid & 15);
        Bs[tid] = Wb[grow];
    }
    for (int i = tid; i < 64 * 16; i += NTHR) Cs[i] = 0.f;
    __syncthreads();

    const int warp = tid >> 5, lane = tid & 31;
    const int wm = warp & 1, wn = warp >> 1;       // warp grid 2x2, warp tile 32x32
    const int gid = lane >> 2, tg = lane & 3;

    for (int s = 0; s < L_SEQ; ++s) {
        float acc[2][4][4];
        #pragma unroll
        for (int mt = 0; mt < 2; ++mt)
            #pragma unroll
            for (int nt = 0; nt < 4; ++nt)
                #pragma unroll
                for (int q = 0; q < 4; ++q) acc[mt][nt][q] = 0.f;

        const float* Hsrc = &g_H[s & 1][cm * 64][0];                       // [64][512]
        const float* Xsrc = g_Xe + ((size_t)s * NB + cm * 64) * EMB;       // [64][256]

        for (int c = 0; c < KTOT / KCH; ++c) {       // 12 chunks: 0..7 from H, 8..11 from Xe
            // stage 64x64 A chunk into smem
            #pragma unroll
            for (int j = 0; j < 8; ++j) {
                int p = tid + NTHR * j;
                int r = p >> 4, q = p & 15;
                float4 v;
                if (c < 8) v = __ldcg((const float4*)(Hsrc + r * HID + c * KCH + q * 4));
                else       v = *(const float4*)(Xsrc + r * EMB + (c - 8) * KCH + q * 4);
                *(float4*)(As + r * SA + q * 4) = v;
            }
            __syncthreads();

            #pragma unroll
            for (int kk = 0; kk < KCH; kk += 8) {
                unsigned a[2][4], b[4][2];
                #pragma unroll
                for (int mt = 0; mt < 2; ++mt) {
                    const float* ap = As + (wm * 32 + mt * 16 + gid) * SA + kk + tg;
                    a[mt][0] = __float_as_uint(ap[0]);
                    a[mt][2] = __float_as_uint(ap[4]);
                    const float* ap8 = ap + 8 * SA;
                    a[mt][1] = __float_as_uint(ap8[0]);
                    a[mt][3] = __float_as_uint(ap8[4]);
                }
                #pragma unroll
                for (int nt = 0; nt < 4; ++nt) {
                    const float* bp = Ws + (wn * 32 + nt * 8 + gid) * SW + c * KCH + kk + tg;
                    b[nt][0] = __float_as_uint(bp[0]);
                    b[nt][1] = __float_as_uint(bp[4]);
                }
                #pragma unroll
                for (int mt = 0; mt < 2; ++mt)
                    #pragma unroll
                    for (int nt = 0; nt < 4; ++nt)
                        mma_tf32(acc[mt][nt], a[mt], b[nt]);
            }
            __syncthreads();
        }

        // store G (64x64) into As buffer, stride SA
        #pragma unroll
        for (int mt = 0; mt < 2; ++mt)
            #pragma unroll
            for (int nt = 0; nt < 4; ++nt) {
                float* gp = As + (wm * 32 + mt * 16 + gid) * SA + wn * 32 + nt * 8 + tg * 2;
                gp[0] = acc[mt][nt][0];
                gp[1] = acc[mt][nt][1];
                gp[8 * SA]     = acc[mt][nt][2];
                gp[8 * SA + 1] = acc[mt][nt][3];
            }
        __syncthreads();

        // epilogue: gates, cell update, H write
        float* Hdst = &g_H[(s + 1) & 1][0][0];
        #pragma unroll
        for (int j = 0; j < 8; ++j) {
            int p = tid + NTHR * j;
            int r = p >> 4, u = p & 15;
            float gF = As[r * SA + u]       + Bs[u];
            float gI = As[r * SA + 16 + u]  + Bs[16 + u];
            float gO = As[r * SA + 32 + u]  + Bs[32 + u];
            float gT = As[r * SA + 48 + u]  + Bs[48 + u];
            float F = sigf(gF), I = sigf(gI), O = sigf(gO);
            float T = tanhfast(gT);
            float cNew = F * Cs[r * 16 + u] + I * T;
            Cs[r * 16 + u] = cNew;
            float h = O * tanhfast(cNew);
            int gr = cm * 64 + r, gc = cn * 16 + u;
            if (s == L_SEQ - 1) out[gr * HID + gc] = h;
            __stcg(Hdst + gr * HID + gc, tf32r(h));
        }

        // grid barrier (monotonic counter; all 64 CTAs co-resident, 1 CTA/SM)
        __threadfence();
        __syncthreads();
        if (tid == 0) {
            unsigned target = (unsigned)NCTA * (unsigned)(s + 1);
            atomicAdd(&g_bar, 1u);
            while (atomicAdd(&g_bar, 0u) < target) { }
            __threadfence();
        }
        __syncthreads();
    }
}

extern "C" void kernel_launch(void* const* d_in, const int* in_sizes, int n_in,
                              void* d_out, int out_size) {
    const int*   X  = (const int*)d_in[0];
    const float* E  = (const float*)d_in[1];
    const float* Ww = (const float*)d_in[2];
    const float* Wb = (const float*)d_in[3];
    float* out = (float*)d_out;

    cudaFuncSetAttribute(lstm_rec, cudaFuncAttributeMaxDynamicSharedMemorySize, SMEM_BYTES);

    lstm_init<<<256, 256>>>();
    lstm_gather<<<(L_SEQ * NB) / 8, 256>>>(X, E);
    lstm_rec<<<NCTA, NTHR, SMEM_BYTES>>>(Ww, Wb, out);
}

// round 8
// speedup vs baseline: 1.2691x; 1.2691x over previous
#include <cuda_runtime.h>
#include <cuda_bf16.h>
#include <math.h>

// Problem constants
#define L_SEQ   2048
#define NB      128      // batch
#define HID     512
#define EMB     256
#define G4H     2048     // 4*HID
#define KREC    512      // in-loop K (H part only; x part precomputed)
#define NCTA    64       // 2 M-tiles x 32 N-slices
#define NTHR    128      // 4 warps
#define KCH     64       // K chunk per pipeline stage (8 chunks)
#define SWR     516      // W smem row stride (floats), %32==4 -> conflict-free frags
#define SA      68       // A/G/X smem row stride (floats), %32==4

// Scratch (device globals: allocation-free rule)
__device__ float    g_H[2][NB][HID];                          // ping-pong H
__device__ float    g_Xpre[(size_t)L_SEQ * NB * G4H];         // 2.1 GB: Xe@Wx^T + b
__device__ unsigned g_bar;                                    // grid barrier (monotonic per launch)

// rec smem: W(64x516) + 2 A bufs(64x68) + X(64x68) + C(64x16)
#define REC_SMEM ((64*SWR + 3*64*SA + 64*16) * 4)
// xpre smem: A(128x68) + B(128x68) + rowvocab(128 ints)
#define XP_SMEM  ((2*128*SA) * 4 + 128 * 4)

__device__ __forceinline__ float tf32r(float x) {
    unsigned u;
    asm("cvt.rna.tf32.f32 %0, %1;" : "=r"(u) : "f"(x));
    return __uint_as_float(u);
}
__device__ __forceinline__ float sigf(float x) { return 1.f / (1.f + __expf(-x)); }
__device__ __forceinline__ float tanhfast(float x) {
    x = fminf(fmaxf(x, -15.f), 15.f);
    float e = __expf(2.f * x);
    return (e - 1.f) / (e + 1.f);
}
__device__ __forceinline__ void mma_tf32(float* d, const unsigned* a, const unsigned* b) {
    asm volatile(
        "mma.sync.aligned.m16n8k8.row.col.f32.tf32.tf32.f32 "
        "{%0,%1,%2,%3}, {%4,%5,%6,%7}, {%8,%9}, {%0,%1,%2,%3};"
        : "+f"(d[0]), "+f"(d[1]), "+f"(d[2]), "+f"(d[3])
        : "r"(a[0]), "r"(a[1]), "r"(a[2]), "r"(a[3]), "r"(b[0]), "r"(b[1]));
}
__device__ __forceinline__ void cp16(float* dst_smem, const float* src) {
    unsigned d = (unsigned)__cvta_generic_to_shared(dst_smem);
    asm volatile("cp.async.cg.shared.global [%0], [%1], 16;" :: "r"(d), "l"(src));
}
__device__ __forceinline__ void cp_commit() { asm volatile("cp.async.commit_group;"); }
template<int N> __device__ __forceinline__ void cp_wait() {
    asm volatile("cp.async.wait_group %0;" :: "n"(N));
}

// ---------------- init: reset barrier + zero H[0] ----------------
__global__ void lstm_init() {
    int i = blockIdx.x * blockDim.x + threadIdx.x;
    if (i == 0) g_bar = 0u;
    if (i < NB * HID) ((float*)g_H)[i] = 0.f;
}

// ---------------- Xpre GEMM: Xpre[t*128+n][j] = E[X[n,t]] . Wx[j] + b[j] ------
// M=262144 (row=t*128+n), N=2048, K=256. CTA tile 128x128, 8 warps (2x4), warp
// tile 64x32. Embedding gather fused into A staging.
__global__ void __launch_bounds__(256, 2)
lstm_xpre(const int* __restrict__ X, const float* __restrict__ E,
          const float* __restrict__ Ww, const float* __restrict__ Wb) {
    extern __shared__ float sm[];
    float* Asm = sm;                 // [128][68]
    float* Bsm = sm + 128 * SA;      // [128][68]
    int*   Vr  = (int*)(sm + 2 * 128 * SA);  // [128] vocab ids

    const int tid = threadIdx.x;
    const int m0 = blockIdx.x * 128;      // row tile
    const int n0 = blockIdx.y * 128;      // gate-col tile

    if (tid < 128) {
        int rid = m0 + tid;
        int t = rid >> 7, n = rid & (NB - 1);
        Vr[tid] = X[n * L_SEQ + t];
    }
    __syncthreads();

    const int warp = tid >> 5, lane = tid & 31;
    const int wm = warp & 1, wn = warp >> 1;       // 2x4 warp grid
    const int gid = lane >> 2, tg = lane & 3;

    float acc[4][4][4];
    #pragma unroll
    for (int mt = 0; mt < 4; ++mt)
        #pragma unroll
        for (int nt = 0; nt < 4; ++nt)
            #pragma unroll
            for (int q = 0; q < 4; ++q) acc[mt][nt][q] = 0.f;

    for (int c = 0; c < EMB / KCH; ++c) {   // 4 chunks
        __syncthreads();
        // stage A: 128 rows x 64 (gathered embedding cols), tf32-rounded
        #pragma unroll
        for (int j = 0; j < 8; ++j) {
            int p = tid + 256 * j;          // 0..2047
            int r = p >> 4, q = p & 15;
            const float4 v = *(const float4*)(E + (size_t)Vr[r] * EMB + c * KCH + q * 4);
            float4 w; w.x = tf32r(v.x); w.y = tf32r(v.y); w.z = tf32r(v.z); w.w = tf32r(v.w);
            *(float4*)(Asm + r * SA + q * 4) = w;
        }
        // stage B: 128 W rows (gate cols n0..n0+127) x 64 (K offset 512+c*64)
        #pragma unroll
        for (int j = 0; j < 8; ++j) {
            int p = tid + 256 * j;
            int r = p >> 4, q = p & 15;
            const float4 v = *(const float4*)(Ww + (size_t)(n0 + r) * (HID + EMB) + HID + c * KCH + q * 4);
            float4 w; w.x = tf32r(v.x); w.y = tf32r(v.y); w.z = tf32r(v.z); w.w = tf32r(v.w);
            *(float4*)(Bsm + r * SA + q * 4) = w;
        }
        __syncthreads();

        #pragma unroll
        for (int kk = 0; kk < KCH; kk += 8) {
            unsigned a[4][4], b[4][2];
            #pragma unroll
            for (int mt = 0; mt < 4; ++mt) {
                const float* ap = Asm + (wm * 64 + mt * 16 + gid) * SA + kk + tg;
                a[mt][0] = __float_as_uint(ap[0]);
                a[mt][2] = __float_as_uint(ap[4]);
                const float* ap8 = ap + 8 * SA;
                a[mt][1] = __float_as_uint(ap8[0]);
                a[mt][3] = __float_as_uint(ap8[4]);
            }
            #pragma unroll
            for (int nt = 0; nt < 4; ++nt) {
                const float* bp = Bsm + (wn * 32 + nt * 8 + gid) * SA + kk + tg;
                b[nt][0] = __float_as_uint(bp[0]);
                b[nt][1] = __float_as_uint(bp[4]);
            }
            #pragma unroll
            for (int mt = 0; mt < 4; ++mt)
                #pragma unroll
                for (int nt = 0; nt < 4; ++nt)
                    mma_tf32(acc[mt][nt], a[mt], b[nt]);
        }
    }

    // epilogue: + bias, store fp32
    #pragma unroll
    for (int nt = 0; nt < 4; ++nt) {
        int col = n0 + wn * 32 + nt * 8 + tg * 2;
        float wb0 = Wb[col], wb1 = Wb[col + 1];
        #pragma unroll
        for (int mt = 0; mt < 4; ++mt) {
            int r0 = m0 + wm * 64 + mt * 16 + gid;
            float2 v0 = make_float2(acc[mt][nt][0] + wb0, acc[mt][nt][1] + wb1);
            float2 v1 = make_float2(acc[mt][nt][2] + wb0, acc[mt][nt][3] + wb1);
            *(float2*)(g_Xpre + (size_t)r0 * G4H + col) = v0;
            *(float2*)(g_Xpre + (size_t)(r0 + 8) * G4H + col) = v1;
        }
    }
}

// ---------------- persistent recurrent kernel ----------------
__global__ void __launch_bounds__(NTHR, 1)
lstm_rec(const float* __restrict__ Ww, float* __restrict__ out) {
    extern __shared__ float sm[];
    float* Ws  = sm;                        // [64][516]  Wh slice, tf32
    float* Ab0 = sm + 64 * SWR;             // [64][68]   A buf 0 (also G buffer)
    float* Ab1 = Ab0 + 64 * SA;             // [64][68]   A buf 1
    float* Xs  = Ab1 + 64 * SA;             // [64][68]   Xpre slice (incl. bias)
    float* Cs  = Xs + 64 * SA;              // [64][16]   cell state

    const int tid = threadIdx.x;
    const int cm  = blockIdx.x & 1;         // M tile: rows cm*64..+64
    const int cn  = blockIdx.x >> 1;        // N slice: hidden units cn*16..+16

    // Load W slice (tf32): local col n -> gate g=n/16, unit u=n%16,
    // global row = g*512 + cn*16 + u; K cols 0..511 (H part only).
    for (int n = 0; n < 64; ++n) {
        int grow = (n >> 4) * HID + cn * 16 + (n & 15);
        const float* src = Ww + (size_t)grow * (HID + EMB);
        for (int k = tid; k < KREC; k += NTHR) Ws[n * SWR + k] = tf32r(src[k]);
    }
    for (int i = tid; i < 64 * 16; i += NTHR) Cs[i] = 0.f;
    __syncthreads();

    const int warp = tid >> 5, lane = tid & 31;
    const int wm = warp & 1, wn = warp >> 1;      // 2x2 warp grid, 32x32 warp tile
    const int gid = lane >> 2, tg = lane & 3;

    float* bufs[2] = {Ab0, Ab1};

    for (int s = 0; s < L_SEQ; ++s) {
        const float* Hsrc = &g_H[s & 1][cm * 64][0];   // [64][512]

        // group 0: H chunk 0 + Xpre slice (incl. folded bias)
        {
            #pragma unroll
            for (int j = 0; j < 8; ++j) {
                int p = tid + NTHR * j;
                int r = p >> 4, q = p & 15;
                cp16(Ab0 + r * SA + q * 4, Hsrc + r * HID + q * 4);
            }
            const float* Xbase = g_Xpre + ((size_t)s * NB + cm * 64) * G4H;
            #pragma unroll
            for (int j = 0; j < 8; ++j) {
                int p = tid + NTHR * j;
                int r = p >> 4, g = (p >> 2) & 3, q = p & 3;
                cp16(Xs + r * SA + g * 16 + q * 4,
                     Xbase + (size_t)r * G4H + g * HID + cn * 16 + q * 4);
            }
            cp_commit();
        }

        float acc[2][4][4];
        #pragma unroll
        for (int mt = 0; mt < 2; ++mt)
            #pragma unroll
            for (int nt = 0; nt < 4; ++nt)
                #pragma unroll
                for (int q = 0; q < 4; ++q) acc[mt][nt][q] = 0.f;

        for (int c = 0; c < KREC / KCH; ++c) {   // 8 chunks, 2-stage pipeline
            if (c < 7) {
                float* nb = bufs[(c + 1) & 1];
                #pragma unroll
                for (int j = 0; j < 8; ++j) {
                    int p = tid + NTHR * j;
                    int r = p >> 4, q = p & 15;
                    cp16(nb + r * SA + q * 4, Hsrc + r * HID + (c + 1) * KCH + q * 4);
                }
                cp_commit();
                cp_wait<1>();
            } else {
                cp_wait<0>();
            }
            __syncthreads();

            const float* buf = bufs[c & 1];
            #pragma unroll
            for (int kk = 0; kk < KCH; kk += 8) {
                unsigned a[2][4], b[4][2];
                #pragma unroll
                for (int mt = 0; mt < 2; ++mt) {
                    const float* ap = buf + (wm * 32 + mt * 16 + gid) * SA + kk + tg;
                    a[mt][0] = __float_as_uint(ap[0]);
                    a[mt][2] = __float_as_uint(ap[4]);
                    const float* ap8 = ap + 8 * SA;
                    a[mt][1] = __float_as_uint(ap8[0]);
                    a[mt][3] = __float_as_uint(ap8[4]);
                }
                #pragma unroll
                for (int nt = 0; nt < 4; ++nt) {
                    const float* bp = Ws + (wn * 32 + nt * 8 + gid) * SWR + c * KCH + kk + tg;
                    b[nt][0] = __float_as_uint(bp[0]);
                    b[nt][1] = __float_as_uint(bp[4]);
                }
                #pragma unroll
                for (int mt = 0; mt < 2; ++mt)
                    #pragma unroll
                    for (int nt = 0; nt < 4; ++nt)
                        mma_tf32(acc[mt][nt], a[mt], b[nt]);
            }
            __syncthreads();
        }

        // store G (64x64) into Ab0 (free: last compute used Ab1)
        #pragma unroll
        for (int mt = 0; mt < 2; ++mt)
            #pragma unroll
            for (int nt = 0; nt < 4; ++nt) {
                float* gp = Ab0 + (wm * 32 + mt * 16 + gid) * SA + wn * 32 + nt * 8 + tg * 2;
                gp[0] = acc[mt][nt][0];
                gp[1] = acc[mt][nt][1];
                gp[8 * SA]     = acc[mt][nt][2];
                gp[8 * SA + 1] = acc[mt][nt][3];
            }
        __syncthreads();

        // epilogue: gates (G + Xpre-with-bias), cell update, H write
        float* Hdst = &g_H[(s + 1) & 1][0][0];
        #pragma unroll
        for (int j = 0; j < 8; ++j) {
            int p = tid + NTHR * j;
            int r = p >> 4, u = p & 15;
            int base = r * SA;
            float gF = Ab0[base + u]      + Xs[base + u];
            float gI = Ab0[base + 16 + u] + Xs[base + 16 + u];
            float gO = Ab0[base + 32 + u] + Xs[base + 32 + u];
            float gT = Ab0[base + 48 + u] + Xs[base + 48 + u];
            float F = sigf(gF), I = sigf(gI), O = sigf(gO);
            float T = tanhfast(gT);
            float cNew = F * Cs[r * 16 + u] + I * T;
            Cs[r * 16 + u] = cNew;
            float h = O * tanhfast(cNew);
            int gr = cm * 64 + r, gc = cn * 16 + u;
            if (s == L_SEQ - 1) out[gr * HID + gc] = h;
            __stcg(Hdst + gr * HID + gc, tf32r(h));
        }

        // grid barrier: one arrive atomic, acquire-load spin (no atomic polling)
        __threadfence();
        __syncthreads();
        if (tid == 0) {
            unsigned target = (unsigned)NCTA * (unsigned)(s + 1);
            atomicAdd(&g_bar, 1u);
            unsigned v;
            do {
                asm volatile("ld.acquire.gpu.global.u32 %0, [%1];"
                             : "=r"(v) : "l"(&g_bar) : "memory");
            } while (v < target);
        }
        __syncthreads();
    }
}

extern "C" void kernel_launch(void* const* d_in, const int* in_sizes, int n_in,
                              void* d_out, int out_size) {
    const int*   X  = (const int*)d_in[0];
    const float* E  = (const float*)d_in[1];
    const float* Ww = (const float*)d_in[2];
    const float* Wb = (const float*)d_in[3];
    float* out = (float*)d_out;

    cudaFuncSetAttribute(lstm_xpre, cudaFuncAttributeMaxDynamicSharedMemorySize, XP_SMEM);
    cudaFuncSetAttribute(lstm_rec,  cudaFuncAttributeMaxDynamicSharedMemorySize, REC_SMEM);

    lstm_init<<<256, 256>>>();
    lstm_xpre<<<dim3(L_SEQ * NB / 128, G4H / 128), 256, XP_SMEM>>>(X, E, Ww, Wb);
    lstm_rec<<<NCTA, NTHR, REC_SMEM>>>(Ww, out);
}

// round 11
// speedup vs baseline: 1.9780x; 1.5586x over previous
#include <cuda_runtime.h>
#include <cuda_fp16.h>
#include <math.h>

// Problem constants
#define L_SEQ   2048
#define NB      128      // batch
#define HID     512
#define EMB     256
#define G4H     2048     // 4*HID
#define NCTA    64       // 2 M-tiles x 32 N-slices
#define NTHR    256      // 8 warps (2x4 warp grid)
#define KCH     128      // halves per staged chunk (4 chunks of K)
#define SWH     520      // W smem row stride (halves): 520/2=260, 260%32==4 -> conflict-free
#define SAH     136      // A chunk row stride (halves): 136/2=68%32==4; 272B row, 16B-aligned
#define SXH     80       // Xpre slice row stride (halves): 160B row, 16B-aligned
#define SG      68       // G row stride (floats): 68%32==4

// Scratch (device globals: allocation-free rule)
__device__ __half   g_H[2][NB][HID];                          // ping-pong H (fp16)
__device__ __half   g_Xpre[(size_t)L_SEQ * NB * G4H];         // 1.07 GB: Xe@Wx^T + b (fp16)
__device__ unsigned g_bar;                                    // grid barrier (monotonic per launch)

// rec smem layout (bytes): G(64x68 f32) | C(64x16 f32) | W(64x520 h)
//                          | Ab0(64x136 h) | Ab1 | Xs(64x80 h)
#define OFF_G    0
#define OFF_C    (OFF_G + 64*SG*4)
#define OFF_W    (OFF_C + 64*16*4)
#define OFF_A0   (OFF_W + 64*SWH*2)
#define OFF_A1   (OFF_A0 + 64*SAH*2)
#define OFF_X    (OFF_A1 + 64*SAH*2)
#define REC_SMEM (OFF_X + 64*SXH*2)

// xpre smem: A(128x264 h) + B(128x264 h) + vocab(128 int)
#define SXP      264     // 264/2=132%32==4 -> conflict-free
#define XP_SMEM  (2*128*SXP*2 + 128*4)

__device__ __forceinline__ float sigf(float x) { return 1.f / (1.f + __expf(-x)); }
__device__ __forceinline__ float tanhfast(float x) {
    x = fminf(fmaxf(x, -15.f), 15.f);
    float e = __expf(2.f * x);
    return (e - 1.f) / (e + 1.f);
}

// mma.sync m16n8k16 fp16 in, fp32 accum
__device__ __forceinline__ void mma_f16(float* d, const unsigned* a, const unsigned* b) {
    asm volatile(
        "mma.sync.aligned.m16n8k16.row.col.f32.f16.f16.f32 "
        "{%0,%1,%2,%3}, {%4,%5,%6,%7}, {%8,%9}, {%0,%1,%2,%3};"
        : "+f"(d[0]), "+f"(d[1]), "+f"(d[2]), "+f"(d[3])
        : "r"(a[0]), "r"(a[1]), "r"(a[2]), "r"(a[3]), "r"(b[0]), "r"(b[1]));
}
__device__ __forceinline__ void cp16(void* dst_smem, const void* src) {
    unsigned d = (unsigned)__cvta_generic_to_shared(dst_smem);
    asm volatile("cp.async.cg.shared.global [%0], [%1], 16;" :: "r"(d), "l"(src));
}
__device__ __forceinline__ void cp_commit() { asm volatile("cp.async.commit_group;"); }
template<int N> __device__ __forceinline__ void cp_wait() {
    asm volatile("cp.async.wait_group %0;" :: "n"(N));
}
__device__ __forceinline__ void st_cg_h(__half* p, __half v) {
    unsigned short us = __half_as_ushort(v);
    asm volatile("st.global.cg.b16 [%0], %1;" :: "l"(p), "h"(us));
}

// ---------------- init: reset barrier + zero H[0] ----------------
__global__ void lstm_init() {
    int i = blockIdx.x * blockDim.x + threadIdx.x;
    if (i == 0) g_bar = 0u;
    if (i < NB * HID) ((__half*)g_H)[i] = __ushort_as_half((unsigned short)0);
}

// ---------------- Xpre GEMM: Xpre[t*128+n][j] = E[X[n,t]] . Wx[j] + b[j] ------
// M=262144 (row=t*128+n), N=2048, K=256 staged fully. CTA tile 128x128, 8 warps
// (2x4), warp tile 64x32, fp16 mma. Embedding gather fused into A staging.
__global__ void __launch_bounds__(256, 1)
lstm_xpre(const int* __restrict__ X, const float* __restrict__ E,
          const float* __restrict__ Ww, const float* __restrict__ Wb) {
    extern __shared__ char smraw[];
    __half* Ah = (__half*)smraw;               // [128][264]
    __half* Bh = Ah + 128 * SXP;               // [128][264]
    int*    Vr = (int*)(Bh + 128 * SXP);       // [128]

    const int tid = threadIdx.x;
    const int m0 = blockIdx.x * 128;
    const int n0 = blockIdx.y * 128;

    if (tid < 128) {
        int rid = m0 + tid;
        int t = rid >> 7, n = rid & (NB - 1);
        Vr[tid] = X[n * L_SEQ + t];
    }
    __syncthreads();

    // stage A: gather 128 embedding rows (256 f32 -> 256 h each)
    #pragma unroll
    for (int j = 0; j < 32; ++j) {
        int p = tid + 256 * j;          // 0..8191 float4s
        int r = p >> 6, q = p & 63;
        const float4 v = *(const float4*)(E + (size_t)Vr[r] * EMB + q * 4);
        __half* dst = Ah + r * SXP + q * 4;
        *(__half2*)dst       = __floats2half2_rn(v.x, v.y);
        *(__half2*)(dst + 2) = __floats2half2_rn(v.z, v.w);
    }
    // stage B: 128 W rows (gate cols n0..), K offset 512 (x part)
    #pragma unroll
    for (int j = 0; j < 32; ++j) {
        int p = tid + 256 * j;
        int r = p >> 6, q = p & 63;
        const float4 v = *(const float4*)(Ww + (size_t)(n0 + r) * (HID + EMB) + HID + q * 4);
        __half* dst = Bh + r * SXP + q * 4;
        *(__half2*)dst       = __floats2half2_rn(v.x, v.y);
        *(__half2*)(dst + 2) = __floats2half2_rn(v.z, v.w);
    }
    __syncthreads();

    const int warp = tid >> 5, lane = tid & 31;
    const int wm = warp & 1, wn = warp >> 1;       // 2x4
    const int gid = lane >> 2, tg = lane & 3;

    float acc[4][4][4];
    #pragma unroll
    for (int mt = 0; mt < 4; ++mt)
        #pragma unroll
        for (int nt = 0; nt < 4; ++nt)
            #pragma unroll
            for (int q = 0; q < 4; ++q) acc[mt][nt][q] = 0.f;

    #pragma unroll
    for (int kk = 0; kk < 16; ++kk) {              // K=256, 16 per mma
        unsigned a[4][4], b[4][2];
        #pragma unroll
        for (int mt = 0; mt < 4; ++mt) {
            const __half* ap = Ah + (wm * 64 + mt * 16 + gid) * SXP + kk * 16 + 2 * tg;
            a[mt][0] = *(const unsigned*)ap;
            a[mt][1] = *(const unsigned*)(ap + 8 * SXP);
            a[mt][2] = *(const unsigned*)(ap + 8);
            a[mt][3] = *(const unsigned*)(ap + 8 * SXP + 8);
        }
        #pragma unroll
        for (int nt = 0; nt < 4; ++nt) {
            const __half* bp = Bh + (wn * 32 + nt * 8 + gid) * SXP + kk * 16 + 2 * tg;
            b[nt][0] = *(const unsigned*)bp;
            b[nt][1] = *(const unsigned*)(bp + 8);
        }
        #pragma unroll
        for (int mt = 0; mt < 4; ++mt)
            #pragma unroll
            for (int nt = 0; nt < 4; ++nt)
                mma_f16(acc[mt][nt], a[mt], b[nt]);
    }

    // epilogue: + bias, store fp16
    #pragma unroll
    for (int nt = 0; nt < 4; ++nt) {
        int col = n0 + wn * 32 + nt * 8 + tg * 2;
        float wb0 = Wb[col], wb1 = Wb[col + 1];
        #pragma unroll
        for (int mt = 0; mt < 4; ++mt) {
            int r0 = m0 + wm * 64 + mt * 16 + gid;
            *(__half2*)(g_Xpre + (size_t)r0 * G4H + col) =
                __floats2half2_rn(acc[mt][nt][0] + wb0, acc[mt][nt][1] + wb1);
            *(__half2*)(g_Xpre + (size_t)(r0 + 8) * G4H + col) =
                __floats2half2_rn(acc[mt][nt][2] + wb0, acc[mt][nt][3] + wb1);
        }
    }
}

// ---------------- persistent recurrent kernel ----------------
// 64 CTAs (2 M-tiles x 32 N-slices of 16 hidden units x 4 gates). 8 warps,
// warp tile 32x16, fp16 mma, K=512 in 4 chunks of 128, 2-stage cp.async pipe.
__global__ void __launch_bounds__(NTHR, 1)
lstm_rec(const float* __restrict__ Ww, float* __restrict__ out) {
    extern __shared__ char smraw[];
    float*  Gs  = (float*)(smraw + OFF_G);    // [64][68]
    float*  Cs  = (float*)(smraw + OFF_C);    // [64][16]
    __half* Ws  = (__half*)(smraw + OFF_W);   // [64][520]
    __half* Ab0 = (__half*)(smraw + OFF_A0);  // [64][136]
    __half* Ab1 = (__half*)(smraw + OFF_A1);  // [64][136]
    __half* Xsh = (__half*)(smraw + OFF_X);   // [64][80]

    const int tid = threadIdx.x;
    const int cm  = blockIdx.x & 1;
    const int cn  = blockIdx.x >> 1;

    // W slice: local col n -> gate g=n/16, unit u=n%16; global row g*512+cn*16+u;
    // K cols 0..511 (H part)
    for (int n = 0; n < 64; ++n) {
        int grow = (n >> 4) * HID + cn * 16 + (n & 15);
        const float* src = Ww + (size_t)grow * (HID + EMB);
        for (int k = tid; k < HID; k += NTHR) Ws[n * SWH + k] = __float2half(src[k]);
    }
    for (int i = tid; i < 64 * 16; i += NTHR) Cs[i] = 0.f;
    __syncthreads();

    const int warp = tid >> 5, lane = tid & 31;
    const int wm = warp & 1, wn = warp >> 1;       // 2x4 grid, 32x16 warp tile
    const int gid = lane >> 2, tg = lane & 3;

    __half* bufs[2] = {Ab0, Ab1};

    for (int s = 0; s < L_SEQ; ++s) {
        const __half* Hsrc = &g_H[s & 1][cm * 64][0];   // [64][512] halves

        // group 0: H chunk 0 + Xpre slice
        {
            #pragma unroll
            for (int j = 0; j < 4; ++j) {
                int p = tid + NTHR * j;           // 0..1023
                int r = p >> 4, q = p & 15;
                cp16(Ab0 + r * SAH + q * 8, Hsrc + r * HID + q * 8);
            }
            const __half* Xbase = g_Xpre + ((size_t)s * NB + cm * 64) * G4H;
            #pragma unroll
            for (int j = 0; j < 2; ++j) {
                int p = tid + NTHR * j;           // 0..511
                int r = p >> 3, g = (p >> 1) & 3, q = p & 1;
                cp16(Xsh + r * SXH + g * 16 + q * 8,
                     Xbase + (size_t)r * G4H + g * HID + cn * 16 + q * 8);
            }
            cp_commit();
        }

        float acc[2][2][4];
        #pragma unroll
        for (int mt = 0; mt < 2; ++mt)
            #pragma unroll
            for (int nt = 0; nt < 2; ++nt)
                #pragma unroll
                for (int q = 0; q < 4; ++q) acc[mt][nt][q] = 0.f;

        for (int c = 0; c < HID / KCH; ++c) {     // 4 chunks
            if (c < 3) {
                __half* nb = bufs[(c + 1) & 1];
                #pragma unroll
                for (int j = 0; j < 4; ++j) {
                    int p = tid + NTHR * j;
                    int r = p >> 4, q = p & 15;
                    cp16(nb + r * SAH + q * 8, Hsrc + r * HID + (c + 1) * KCH + q * 8);
                }
                cp_commit();
                cp_wait<1>();
            } else {
                cp_wait<0>();
            }
            __syncthreads();

            const __half* buf = bufs[c & 1];
            #pragma unroll
            for (int kk = 0; kk < KCH / 16; ++kk) {   // 8 mma-K steps
                unsigned a[2][4], b[2][2];
                #pragma unroll
                for (int mt = 0; mt < 2; ++mt) {
                    const __half* ap = buf + (wm * 32 + mt * 16 + gid) * SAH + kk * 16 + 2 * tg;
                    a[mt][0] = *(const unsigned*)ap;
                    a[mt][1] = *(const unsigned*)(ap + 8 * SAH);
                    a[mt][2] = *(const unsigned*)(ap + 8);
                    a[mt][3] = *(const unsigned*)(ap + 8 * SAH + 8);
                }
                #pragma unroll
                for (int nt = 0; nt < 2; ++nt) {
                    const __half* bp = Ws + (wn * 16 + nt * 8 + gid) * SWH + c * KCH + kk * 16 + 2 * tg;
                    b[nt][0] = *(const unsigned*)bp;
                    b[nt][1] = *(const unsigned*)(bp + 8);
                }
                #pragma unroll
                for (int mt = 0; mt < 2; ++mt)
                    #pragma unroll
                    for (int nt = 0; nt < 2; ++nt)
                        mma_f16(acc[mt][nt], a[mt], b[nt]);
            }
            __syncthreads();
        }

        // store G (64x64 f32)
        #pragma unroll
        for (int mt = 0; mt < 2; ++mt)
            #pragma unroll
            for (int nt = 0; nt < 2; ++nt) {
                float* gp = Gs + (wm * 32 + mt * 16 + gid) * SG + wn * 16 + nt * 8 + tg * 2;
                gp[0] = acc[mt][nt][0];
                gp[1] = acc[mt][nt][1];
                gp[8 * SG]     = acc[mt][nt][2];
                gp[8 * SG + 1] = acc[mt][nt][3];
            }
        __syncthreads();

        // epilogue: gates = G + Xpre(with bias), cell update, H write (fp16)
        __half* Hdst = &g_H[(s + 1) & 1][0][0];
        #pragma unroll
        for (int j = 0; j < 4; ++j) {
            int p = tid + NTHR * j;               // 0..1023
            int r = p >> 4, u = p & 15;
            float gF = Gs[r * SG + u]      + __half2float(Xsh[r * SXH + u]);
            float gI = Gs[r * SG + 16 + u] + __half2float(Xsh[r * SXH + 16 + u]);
            float gO = Gs[r * SG + 32 + u] + __half2float(Xsh[r * SXH + 32 + u]);
            float gT = Gs[r * SG + 48 + u] + __half2float(Xsh[r * SXH + 48 + u]);
            float F = sigf(gF), I = sigf(gI), O = sigf(gO);
            float T = tanhfast(gT);
            float cNew = F * Cs[r * 16 + u] + I * T;
            Cs[r * 16 + u] = cNew;
            float h = O * tanhfast(cNew);
            int gr = cm * 64 + r, gc = cn * 16 + u;
            if (s == L_SEQ - 1) out[gr * HID + gc] = h;
            st_cg_h(Hdst + gr * HID + gc, __float2half(h));
        }

        // grid barrier: one arrive atomic, acquire-load spin
        __threadfence();
        __syncthreads();
        if (tid == 0) {
            unsigned target = (unsigned)NCTA * (unsigned)(s + 1);
            atomicAdd(&g_bar, 1u);
            unsigned v;
            do {
                asm volatile("ld.acquire.gpu.global.u32 %0, [%1];"
                             : "=r"(v) : "l"(&g_bar) : "memory");
            } while (v < target);
        }
        __syncthreads();
    }
}

extern "C" void kernel_launch(void* const* d_in, const int* in_sizes, int n_in,
                              void* d_out, int out_size) {
    const int*   X  = (const int*)d_in[0];
    const float* E  = (const float*)d_in[1];
    const float* Ww = (const float*)d_in[2];
    const float* Wb = (const float*)d_in[3];
    float* out = (float*)d_out;

    cudaFuncSetAttribute(lstm_xpre, cudaFuncAttributeMaxDynamicSharedMemorySize, XP_SMEM);
    cudaFuncSetAttribute(lstm_rec,  cudaFuncAttributeMaxDynamicSharedMemorySize, REC_SMEM);

    lstm_init<<<256, 256>>>();
    lstm_xpre<<<dim3(L_SEQ * NB / 128, G4H / 128), 256, XP_SMEM>>>(X, E, Ww, Wb);
    lstm_rec<<<NCTA, NTHR, REC_SMEM>>>(Ww, out);
}

// round 16
// speedup vs baseline: 3.0788x; 1.5565x over previous
#include <cuda_runtime.h>
#include <cuda_fp16.h>
#include <math.h>

// Problem constants
#define L_SEQ   2048
#define NB      128      // batch
#define HID     512
#define EMB     256
#define G4H     2048     // 4*HID
#define NCTA    64       // 2 M-tiles x 32 N-slices
#define NTHR    256      // 8 warps (2x4 warp grid)
#define KCH     128      // halves per chunk (4 chunks of K=512)
#define SWH     520      // W / A-buffer row stride (halves): 1040B % 128B = 16 -> ldmatrix conflict-free
#define SXH     80       // Xpre slice row stride (halves)
#define SG      68       // G row stride (floats)

// Scratch (device globals: allocation-free rule)
__device__ __half   g_H[2][NB][HID];                          // ping-pong H (fp16)
__device__ __half   g_Xpre[(size_t)L_SEQ * NB * G4H];         // 1.07 GB: Xe@Wx^T + b (fp16)
__device__ unsigned g_bar;                                    // grid barrier (monotonic per launch)

// rec smem layout (bytes)
#define OFF_G    0
#define OFF_C    (OFF_G + 64*SG*4)
#define OFF_W    (OFF_C + 64*16*4)
#define OFF_A    (OFF_W + 64*SWH*2)
#define OFF_X0   (OFF_A + 64*SWH*2)
#define OFF_X1   (OFF_X0 + 64*SXH*2)
#define REC_SMEM (OFF_X1 + 64*SXH*2)

// xpre smem: A(128x264 h) + B(128x264 h) + vocab(128 int)
#define SXP      264
#define XP_SMEM  (2*128*SXP*2 + 128*4)

__device__ __forceinline__ float sigf(float x) { return 1.f / (1.f + __expf(-x)); }
__device__ __forceinline__ float tanhfast(float x) {
    x = fminf(fmaxf(x, -15.f), 15.f);
    float e = __expf(2.f * x);
    return (e - 1.f) / (e + 1.f);
}
__device__ __forceinline__ unsigned h2_bits(__half2 h) {
    union { __half2 h; unsigned u; } cv;
    cv.h = h;
    return cv.u;
}

__device__ __forceinline__ void mma_f16(float* d, const unsigned* a, const unsigned* b) {
    asm volatile(
        "mma.sync.aligned.m16n8k16.row.col.f32.f16.f16.f32 "
        "{%0,%1,%2,%3}, {%4,%5,%6,%7}, {%8,%9}, {%0,%1,%2,%3};"
        : "+f"(d[0]), "+f"(d[1]), "+f"(d[2]), "+f"(d[3])
        : "r"(a[0]), "r"(a[1]), "r"(a[2]), "r"(a[3]), "r"(b[0]), "r"(b[1]));
}
__device__ __forceinline__ void ldsm_x4(unsigned* r, unsigned addr) {
    asm volatile("ldmatrix.sync.aligned.m8n8.x4.shared.b16 {%0,%1,%2,%3}, [%4];"
        : "=r"(r[0]), "=r"(r[1]), "=r"(r[2]), "=r"(r[3]) : "r"(addr));
}
__device__ __forceinline__ void cp16(void* dst_smem, const void* src) {
    unsigned d = (unsigned)__cvta_generic_to_shared(dst_smem);
    asm volatile("cp.async.cg.shared.global [%0], [%1], 16;" :: "r"(d), "l"(src));
}
__device__ __forceinline__ void cp_commit() { asm volatile("cp.async.commit_group;"); }
template<int N> __device__ __forceinline__ void cp_wait() {
    asm volatile("cp.async.wait_group %0;" :: "n"(N));
}
__device__ __forceinline__ void ld4h(float* o, const __half* p) {
    __half2 a = *(const __half2*)p, b = *(const __half2*)(p + 2);
    float2 fa = __half22float2(a), fb = __half22float2(b);
    o[0] = fa.x; o[1] = fa.y; o[2] = fb.x; o[3] = fb.y;
}

// ---------------- Xpre GEMM (+ fused init): ---------------------------------
// Xpre[t*128+n][j] = E[X[n,t]] . Wx[j] + b[j].  Block (0,0) also zeroes H[0]
// and resets the barrier (stream order covers lstm_rec's dependence on both).
__global__ void __launch_bounds__(256, 1)
lstm_xpre(const int* __restrict__ X, const float* __restrict__ E,
          const float* __restrict__ Ww, const float* __restrict__ Wb) {
    extern __shared__ char smraw[];
    __half* Ah = (__half*)smraw;               // [128][264]
    __half* Bh = Ah + 128 * SXP;               // [128][264]
    int*    Vr = (int*)(Bh + 128 * SXP);       // [128]

    const int tid = threadIdx.x;
    const int m0 = blockIdx.x * 128;
    const int n0 = blockIdx.y * 128;

    if (blockIdx.x == 0 && blockIdx.y == 0) {
        if (tid == 0) g_bar = 0u;
        for (int i = tid; i < NB * HID / 8; i += 256)       // zero H[0] (uint4)
            ((uint4*)g_H)[i] = make_uint4(0, 0, 0, 0);
    }

    if (tid < 128) {
        int rid = m0 + tid;
        int t = rid >> 7, n = rid & (NB - 1);
        Vr[tid] = X[n * L_SEQ + t];
    }
    __syncthreads();

    // stage A: gather 128 embedding rows (256 f32 -> h)
    #pragma unroll
    for (int j = 0; j < 32; ++j) {
        int p = tid + 256 * j;
        int r = p >> 6, q = p & 63;
        const float4 v = *(const float4*)(E + (size_t)Vr[r] * EMB + q * 4);
        __half* dst = Ah + r * SXP + q * 4;
        *(__half2*)dst       = __floats2half2_rn(v.x, v.y);
        *(__half2*)(dst + 2) = __floats2half2_rn(v.z, v.w);
    }
    // stage B: 128 W rows (gate cols n0..), K offset 512 (x part)
    #pragma unroll
    for (int j = 0; j < 32; ++j) {
        int p = tid + 256 * j;
        int r = p >> 6, q = p & 63;
        const float4 v = *(const float4*)(Ww + (size_t)(n0 + r) * (HID + EMB) + HID + q * 4);
        __half* dst = Bh + r * SXP + q * 4;
        *(__half2*)dst       = __floats2half2_rn(v.x, v.y);
        *(__half2*)(dst + 2) = __floats2half2_rn(v.z, v.w);
    }
    __syncthreads();

    const int warp = tid >> 5, lane = tid & 31;
    const int wm = warp & 1, wn = warp >> 1;       // 2x4
    const int gid = lane >> 2, tg = lane & 3;

    float acc[4][4][4];
    #pragma unroll
    for (int mt = 0; mt < 4; ++mt)
        #pragma unroll
        for (int nt = 0; nt < 4; ++nt)
            #pragma unroll
            for (int q = 0; q < 4; ++q) acc[mt][nt][q] = 0.f;

    #pragma unroll
    for (int kk = 0; kk < 16; ++kk) {
        unsigned a[4][4], b[4][2];
        #pragma unroll
        for (int mt = 0; mt < 4; ++mt) {
            const __half* ap = Ah + (wm * 64 + mt * 16 + gid) * SXP + kk * 16 + 2 * tg;
            a[mt][0] = *(const unsigned*)ap;
            a[mt][1] = *(const unsigned*)(ap + 8 * SXP);
            a[mt][2] = *(const unsigned*)(ap + 8);
            a[mt][3] = *(const unsigned*)(ap + 8 * SXP + 8);
        }
        #pragma unroll
        for (int nt = 0; nt < 4; ++nt) {
            const __half* bp = Bh + (wn * 32 + nt * 8 + gid) * SXP + kk * 16 + 2 * tg;
            b[nt][0] = *(const unsigned*)bp;
            b[nt][1] = *(const unsigned*)(bp + 8);
        }
        #pragma unroll
        for (int mt = 0; mt < 4; ++mt)
            #pragma unroll
            for (int nt = 0; nt < 4; ++nt)
                mma_f16(acc[mt][nt], a[mt], b[nt]);
    }

    #pragma unroll
    for (int nt = 0; nt < 4; ++nt) {
        int col = n0 + wn * 32 + nt * 8 + tg * 2;
        float wb0 = Wb[col], wb1 = Wb[col + 1];
        #pragma unroll
        for (int mt = 0; mt < 4; ++mt) {
            int r0 = m0 + wm * 64 + mt * 16 + gid;
            *(__half2*)(g_Xpre + (size_t)r0 * G4H + col) =
                __floats2half2_rn(acc[mt][nt][0] + wb0, acc[mt][nt][1] + wb1);
            *(__half2*)(g_Xpre + (size_t)(r0 + 8) * G4H + col) =
                __floats2half2_rn(acc[mt][nt][2] + wb0, acc[mt][nt][3] + wb1);
        }
    }
}

// ---------------- persistent recurrent kernel ----------------
// 64 CTAs (2 M x 32 N-slices), 8 warps (2x4), warp tile 32x16, fp16 mma,
// full-H depth-4 cp.async staging, ldmatrix fragments, X(s+1) prefetch.
__global__ void __launch_bounds__(NTHR, 1)
lstm_rec(const float* __restrict__ Ww, float* __restrict__ out) {
    extern __shared__ char smraw[];
    float*  Gs  = (float*)(smraw + OFF_G);    // [64][68]
    float*  Cs  = (float*)(smraw + OFF_C);    // [64][16]
    __half* Ws  = (__half*)(smraw + OFF_W);   // [64][520]
    __half* Ab  = (__half*)(smraw + OFF_A);   // [64][520] (512 used)
    __half* Xb[2] = {(__half*)(smraw + OFF_X0), (__half*)(smraw + OFF_X1)};

    const int tid = threadIdx.x;
    const int cm  = blockIdx.x & 1;
    const int cn  = blockIdx.x >> 1;

    // W slice: local col n -> gate g=n/16, unit u=n%16; global row g*512+cn*16+u
    for (int n = 0; n < 64; ++n) {
        int grow = (n >> 4) * HID + cn * 16 + (n & 15);
        const float* src = Ww + (size_t)grow * (HID + EMB);
        for (int k = tid; k < HID; k += NTHR) Ws[n * SWH + k] = __float2half(src[k]);
    }
    for (int i = tid; i < 64 * 16; i += NTHR) Cs[i] = 0.f;
    __syncthreads();

    const int warp = tid >> 5, lane = tid & 31;
    const int wm = warp & 1, wn = warp >> 1;       // 2x4 grid, 32x16 warp tile
    const int lrow = lane & 7, matid = lane >> 3;

    // ldmatrix base addresses (byte, shared space)
    const unsigned AbS = (unsigned)__cvta_generic_to_shared(Ab);
    const unsigned WbS = (unsigned)__cvta_generic_to_shared(Ws);
    unsigned aAddr[2];
    #pragma unroll
    for (int mt = 0; mt < 2; ++mt)
        aAddr[mt] = AbS + ((wm * 32 + mt * 16 + (matid & 1) * 8 + lrow) * SWH
                           + (matid >> 1) * 8) * 2;
    const unsigned bAddr = WbS + ((wn * 16 + (matid >> 1) * 8 + lrow) * SWH
                                  + (matid & 1) * 8) * 2;

    // epilogue mapping: thread -> (row r, 4 consecutive units q..q+3)
    const int er = tid >> 2, eq = (tid & 3) * 4;

    // prologue: prefetch X(0) into buf 0
    {
        const __half* Xbase = g_Xpre + ((size_t)0 * NB + cm * 64) * G4H;
        #pragma unroll
        for (int j = 0; j < 2; ++j) {
            int p = tid + NTHR * j;
            int r = p >> 3, g = (p >> 1) & 3, q = p & 1;
            cp16(Xb[0] + r * SXH + g * 16 + q * 8,
                 Xbase + (size_t)r * G4H + g * HID + cn * 16 + q * 8);
        }
        cp_commit();
    }

    for (int s = 0; s < L_SEQ; ++s) {
        const __half* Hsrc = &g_H[s & 1][cm * 64][0];   // [64][512] halves

        // issue all 4 H chunks (groups c0..c3) + X(s+1) (group 4)
        #pragma unroll
        for (int c = 0; c < 4; ++c) {
            #pragma unroll
            for (int j = 0; j < 4; ++j) {
                int p = tid + NTHR * j;
                int r = p >> 4, q = p & 15;
                cp16(Ab + r * SWH + c * KCH + q * 8, Hsrc + r * HID + c * KCH + q * 8);
            }
            cp_commit();
        }
        {
            int sn = (s + 1 < L_SEQ) ? s + 1 : s;
            const __half* Xbase = g_Xpre + ((size_t)sn * NB + cm * 64) * G4H;
            __half* xd = Xb[(s + 1) & 1];
            #pragma unroll
            for (int j = 0; j < 2; ++j) {
                int p = tid + NTHR * j;
                int r = p >> 3, g = (p >> 1) & 3, q = p & 1;
                cp16(xd + r * SXH + g * 16 + q * 8,
                     Xbase + (size_t)r * G4H + g * HID + cn * 16 + q * 8);
            }
            cp_commit();
        }

        float acc[2][2][4];
        #pragma unroll
        for (int mt = 0; mt < 2; ++mt)
            #pragma unroll
            for (int nt = 0; nt < 2; ++nt)
                #pragma unroll
                for (int q = 0; q < 4; ++q) acc[mt][nt][q] = 0.f;

        auto chunk = [&](int coff) {
            #pragma unroll
            for (int kk = 0; kk < 8; ++kk) {
                unsigned off = (unsigned)(coff + kk * 16) * 2;
                unsigned a0[4], a1[4], bb[4];
                ldsm_x4(a0, aAddr[0] + off);
                ldsm_x4(a1, aAddr[1] + off);
                ldsm_x4(bb, bAddr + off);
                mma_f16(acc[0][0], a0, bb);
                mma_f16(acc[0][1], a0, bb + 2);
                mma_f16(acc[1][0], a1, bb);
                mma_f16(acc[1][1], a1, bb + 2);
            }
        };
        cp_wait<4>(); __syncthreads(); chunk(0 * KCH);
        cp_wait<3>(); __syncthreads(); chunk(1 * KCH);
        cp_wait<2>(); __syncthreads(); chunk(2 * KCH);
        cp_wait<1>(); __syncthreads(); chunk(3 * KCH);

        // store G (64x64 f32)
        {
            const int gid = lane >> 2, tg = lane & 3;
            #pragma unroll
            for (int mt = 0; mt < 2; ++mt)
                #pragma unroll
                for (int nt = 0; nt < 2; ++nt) {
                    float* gp = Gs + (wm * 32 + mt * 16 + gid) * SG + wn * 16 + nt * 8 + tg * 2;
                    gp[0] = acc[mt][nt][0];
                    gp[1] = acc[mt][nt][1];
                    gp[8 * SG]     = acc[mt][nt][2];
                    gp[8 * SG + 1] = acc[mt][nt][3];
                }
        }
        __syncthreads();

        // epilogue: 4 consecutive units per thread, vectorized
        {
            const __half* xr = Xb[s & 1] + er * SXH;
            const float*  gp = Gs + er * SG;
            float xF[4], xI[4], xO[4], xT[4];
            ld4h(xF, xr + eq); ld4h(xI, xr + 16 + eq);
            ld4h(xO, xr + 32 + eq); ld4h(xT, xr + 48 + eq);
            float4 c4 = *(float4*)(Cs + er * 16 + eq);
            float cc[4] = {c4.x, c4.y, c4.z, c4.w};
            float h[4];
            #pragma unroll
            for (int k = 0; k < 4; ++k) {
                float gF = gp[eq + k]      + xF[k];
                float gI = gp[16 + eq + k] + xI[k];
                float gO = gp[32 + eq + k] + xO[k];
                float gT = gp[48 + eq + k] + xT[k];
                float F = sigf(gF), I = sigf(gI), O = sigf(gO);
                float T = tanhfast(gT);
                cc[k] = F * cc[k] + I * T;
                h[k] = O * tanhfast(cc[k]);
            }
            *(float4*)(Cs + er * 16 + eq) = make_float4(cc[0], cc[1], cc[2], cc[3]);
            int gr = cm * 64 + er, gc = cn * 16 + eq;
            unsigned u01 = h2_bits(__floats2half2_rn(h[0], h[1]));
            unsigned u23 = h2_bits(__floats2half2_rn(h[2], h[3]));
            __half* hp = &g_H[(s + 1) & 1][gr][gc];
            asm volatile("st.global.cg.v2.u32 [%0], {%1, %2};"
                         :: "l"(hp), "r"(u01), "r"(u23));
            if (s == L_SEQ - 1)
                *(float4*)(out + gr * HID + gc) = make_float4(h[0], h[1], h[2], h[3]);
        }

        // grid barrier: release arrive + acquire spin
        __syncthreads();
        if (tid == 0) {
            asm volatile("red.release.gpu.global.add.u32 [%0], %1;"
                         :: "l"(&g_bar), "r"(1u) : "memory");
            unsigned target = (unsigned)NCTA * (unsigned)(s + 1);
            unsigned v;
            do {
                asm volatile("ld.acquire.gpu.global.u32 %0, [%1];"
                             : "=r"(v) : "l"(&g_bar) : "memory");
            } while (v < target);
        }
        __syncthreads();
    }
}

extern "C" void kernel_launch(void* const* d_in, const int* in_sizes, int n_in,
                              void* d_out, int out_size) {
    const int*   X  = (const int*)d_in[0];
    const float* E  = (const float*)d_in[1];
    const float* Ww = (const float*)d_in[2];
    const float* Wb = (const float*)d_in[3];
    float* out = (float*)d_out;

    cudaFuncSetAttribute(lstm_xpre, cudaFuncAttributeMaxDynamicSharedMemorySize, XP_SMEM);
    cudaFuncSetAttribute(lstm_rec,  cudaFuncAttributeMaxDynamicSharedMemorySize, REC_SMEM);

    lstm_xpre<<<dim3(L_SEQ * NB / 128, G4H / 128), 256, XP_SMEM>>>(X, E, Ww, Wb);
    lstm_rec<<<NCTA, NTHR, REC_SMEM>>>(Ww, out);
}

// round 17
// speedup vs baseline: 3.2679x; 1.0614x over previous
#include <cuda_runtime.h>
#include <cuda_fp16.h>
#include <math.h>

// Problem constants
#define L_SEQ   2048
#define NB      128      // batch
#define HID     512
#define EMB     256
#define G4H     2048     // 4*HID
#define NCTA    64       // 2 M-tiles x 32 N-slices
#define NTHR    256      // 8 warps (2x4 warp grid)
#define KCH     128      // halves per full chunk
#define SWH     520      // W / A-buffer row stride (halves): 1040B % 128B = 16 -> ldmatrix conflict-free
#define SXH     80       // Xpre slice row stride (halves)
#define SG      68       // G row stride (floats)

// Scratch (device globals: allocation-free rule)
__device__ __half   g_H[2][NB][HID];                          // ping-pong H (fp16)
__device__ __half   g_Xpre[(size_t)L_SEQ * NB * G4H];         // 1.07 GB: Xe@Wx^T + b (fp16)
__device__ unsigned g_flags[2][32][32];                       // [cm][cn] flags, 128B padded

// rec smem layout (bytes)
#define OFF_G    0
#define OFF_C    (OFF_G + 64*SG*4)
#define OFF_W    (OFF_C + 64*16*4)
#define OFF_A    (OFF_W + 64*SWH*2)
#define OFF_X0   (OFF_A + 64*SWH*2)
#define OFF_X1   (OFF_X0 + 64*SXH*2)
#define REC_SMEM (OFF_X1 + 64*SXH*2)

// xpre smem: A(128x264 h) + B(128x264 h) + vocab(128 int)
#define SXP      264
#define XP_SMEM  (2*128*SXP*2 + 128*4)

__device__ __forceinline__ float sigf(float x) { return 1.f / (1.f + __expf(-x)); }
__device__ __forceinline__ float tanhfast(float x) {
    x = fminf(fmaxf(x, -15.f), 15.f);
    float e = __expf(2.f * x);
    return (e - 1.f) / (e + 1.f);
}
__device__ __forceinline__ unsigned h2_bits(__half2 h) {
    union { __half2 h; unsigned u; } cv;
    cv.h = h;
    return cv.u;
}

__device__ __forceinline__ void mma_f16(float* d, const unsigned* a, const unsigned* b) {
    asm volatile(
        "mma.sync.aligned.m16n8k16.row.col.f32.f16.f16.f32 "
        "{%0,%1,%2,%3}, {%4,%5,%6,%7}, {%8,%9}, {%0,%1,%2,%3};"
        : "+f"(d[0]), "+f"(d[1]), "+f"(d[2]), "+f"(d[3])
        : "r"(a[0]), "r"(a[1]), "r"(a[2]), "r"(a[3]), "r"(b[0]), "r"(b[1]));
}
__device__ __forceinline__ void ldsm_x4(unsigned* r, unsigned addr) {
    asm volatile("ldmatrix.sync.aligned.m8n8.x4.shared.b16 {%0,%1,%2,%3}, [%4];"
        : "=r"(r[0]), "=r"(r[1]), "=r"(r[2]), "=r"(r[3]) : "r"(addr));
}
__device__ __forceinline__ void cp16(void* dst_smem, const void* src) {
    unsigned d = (unsigned)__cvta_generic_to_shared(dst_smem);
    asm volatile("cp.async.cg.shared.global [%0], [%1], 16;" :: "r"(d), "l"(src));
}
__device__ __forceinline__ void cp_commit() { asm volatile("cp.async.commit_group;"); }
template<int N> __device__ __forceinline__ void cp_wait() {
    asm volatile("cp.async.wait_group %0;" :: "n"(N));
}
__device__ __forceinline__ void ld4h(float* o, const __half* p) {
    __half2 a = *(const __half2*)p, b = *(const __half2*)(p + 2);
    float2 fa = __half22float2(a), fb = __half22float2(b);
    o[0] = fa.x; o[1] = fa.y; o[2] = fb.x; o[3] = fb.y;
}
// one kk-step: 2 A ldmatrix + 4 mma against preloaded B fragments
__device__ __forceinline__ void do_kk(float acc[2][2][4], unsigned aAddr0, unsigned aAddr1,
                                      unsigned off, const unsigned* bb) {
    unsigned a0[4], a1[4];
    ldsm_x4(a0, aAddr0 + off);
    ldsm_x4(a1, aAddr1 + off);
    mma_f16(acc[0][0], a0, bb);
    mma_f16(acc[0][1], a0, bb + 2);
    mma_f16(acc[1][0], a1, bb);
    mma_f16(acc[1][1], a1, bb + 2);
}

// ---------------- Xpre GEMM (+ fused init): ---------------------------------
// Xpre[t*128+n][j] = E[X[n,t]] . Wx[j] + b[j].  Block (0,0) also zeroes H[0]
// and the barrier flags (stream order covers lstm_rec's dependence on both).
__global__ void __launch_bounds__(256, 1)
lstm_xpre(const int* __restrict__ X, const float* __restrict__ E,
          const float* __restrict__ Ww, const float* __restrict__ Wb) {
    extern __shared__ char smraw[];
    __half* Ah = (__half*)smraw;               // [128][264]
    __half* Bh = Ah + 128 * SXP;               // [128][264]
    int*    Vr = (int*)(Bh + 128 * SXP);       // [128]

    const int tid = threadIdx.x;
    const int m0 = blockIdx.x * 128;
    const int n0 = blockIdx.y * 128;

    if (blockIdx.x == 0 && blockIdx.y == 0) {
        for (int i = tid; i < 2 * 32 * 32; i += 256) ((unsigned*)g_flags)[i] = 0u;
        for (int i = tid; i < NB * HID / 8; i += 256)       // zero H[0] (uint4)
            ((uint4*)g_H)[i] = make_uint4(0, 0, 0, 0);
    }

    if (tid < 128) {
        int rid = m0 + tid;
        int t = rid >> 7, n = rid & (NB - 1);
        Vr[tid] = X[n * L_SEQ + t];
    }
    __syncthreads();

    // stage A: gather 128 embedding rows (256 f32 -> h)
    #pragma unroll
    for (int j = 0; j < 32; ++j) {
        int p = tid + 256 * j;
        int r = p >> 6, q = p & 63;
        const float4 v = *(const float4*)(E + (size_t)Vr[r] * EMB + q * 4);
        __half* dst = Ah + r * SXP + q * 4;
        *(__half2*)dst       = __floats2half2_rn(v.x, v.y);
        *(__half2*)(dst + 2) = __floats2half2_rn(v.z, v.w);
    }
    // stage B: 128 W rows (gate cols n0..), K offset 512 (x part)
    #pragma unroll
    for (int j = 0; j < 32; ++j) {
        int p = tid + 256 * j;
        int r = p >> 6, q = p & 63;
        const float4 v = *(const float4*)(Ww + (size_t)(n0 + r) * (HID + EMB) + HID + q * 4);
        __half* dst = Bh + r * SXP + q * 4;
        *(__half2*)dst       = __floats2half2_rn(v.x, v.y);
        *(__half2*)(dst + 2) = __floats2half2_rn(v.z, v.w);
    }
    __syncthreads();

    const int warp = tid >> 5, lane = tid & 31;
    const int wm = warp & 1, wn = warp >> 1;       // 2x4
    const int gid = lane >> 2, tg = lane & 3;

    float acc[4][4][4];
    #pragma unroll
    for (int mt = 0; mt < 4; ++mt)
        #pragma unroll
        for (int nt = 0; nt < 4; ++nt)
            #pragma unroll
            for (int q = 0; q < 4; ++q) acc[mt][nt][q] = 0.f;

    #pragma unroll
    for (int kk = 0; kk < 16; ++kk) {
        unsigned a[4][4], b[4][2];
        #pragma unroll
        for (int mt = 0; mt < 4; ++mt) {
            const __half* ap = Ah + (wm * 64 + mt * 16 + gid) * SXP + kk * 16 + 2 * tg;
            a[mt][0] = *(const unsigned*)ap;
            a[mt][1] = *(const unsigned*)(ap + 8 * SXP);
            a[mt][2] = *(const unsigned*)(ap + 8);
            a[mt][3] = *(const unsigned*)(ap + 8 * SXP + 8);
        }
        #pragma unroll
        for (int nt = 0; nt < 4; ++nt) {
            const __half* bp = Bh + (wn * 32 + nt * 8 + gid) * SXP + kk * 16 + 2 * tg;
            b[nt][0] = *(const unsigned*)bp;
            b[nt][1] = *(const unsigned*)(bp + 8);
        }
        #pragma unroll
        for (int mt = 0; mt < 4; ++mt)
            #pragma unroll
            for (int nt = 0; nt < 4; ++nt)
                mma_f16(acc[mt][nt], a[mt], b[nt]);
    }

    #pragma unroll
    for (int nt = 0; nt < 4; ++nt) {
        int col = n0 + wn * 32 + nt * 8 + tg * 2;
        float wb0 = Wb[col], wb1 = Wb[col + 1];
        #pragma unroll
        for (int mt = 0; mt < 4; ++mt) {
            int r0 = m0 + wm * 64 + mt * 16 + gid;
            *(__half2*)(g_Xpre + (size_t)r0 * G4H + col) =
                __floats2half2_rn(acc[mt][nt][0] + wb0, acc[mt][nt][1] + wb1);
            *(__half2*)(g_Xpre + (size_t)(r0 + 8) * G4H + col) =
                __floats2half2_rn(acc[mt][nt][2] + wb0, acc[mt][nt][3] + wb1);
        }
    }
}

// ---------------- persistent recurrent kernel ----------------
// 64 CTAs (2 independent cm-groups x 32 N-slices), 8 warps (2x4), warp tile
// 32x16, fp16 mma, registered B fragments, split first chunk, flag barrier.
__global__ void __launch_bounds__(NTHR, 1)
lstm_rec(const float* __restrict__ Ww, float* __restrict__ out) {
    extern __shared__ char smraw[];
    float*  Gs  = (float*)(smraw + OFF_G);    // [64][68]
    float*  Cs  = (float*)(smraw + OFF_C);    // [64][16]
    __half* Ws  = (__half*)(smraw + OFF_W);   // [64][520]
    __half* Ab  = (__half*)(smraw + OFF_A);   // [64][520] (512 used)
    __half* Xb[2] = {(__half*)(smraw + OFF_X0), (__half*)(smraw + OFF_X1)};

    const int tid = threadIdx.x;
    const int cm  = blockIdx.x & 1;
    const int cn  = blockIdx.x >> 1;

    // W slice: local col n -> gate g=n/16, unit u=n%16; global row g*512+cn*16+u
    for (int n = 0; n < 64; ++n) {
        int grow = (n >> 4) * HID + cn * 16 + (n & 15);
        const float* src = Ww + (size_t)grow * (HID + EMB);
        for (int k = tid; k < HID; k += NTHR) Ws[n * SWH + k] = __float2half(src[k]);
    }
    for (int i = tid; i < 64 * 16; i += NTHR) Cs[i] = 0.f;
    __syncthreads();

    const int warp = tid >> 5, lane = tid & 31;
    const int wm = warp & 1, wn = warp >> 1;       // 2x4 grid, 32x16 warp tile
    const int lrow = lane & 7, matid = lane >> 3;

    // ldmatrix base addresses (byte, shared space)
    const unsigned AbS = (unsigned)__cvta_generic_to_shared(Ab);
    const unsigned WbS = (unsigned)__cvta_generic_to_shared(Ws);
    unsigned aAddr[2];
    #pragma unroll
    for (int mt = 0; mt < 2; ++mt)
        aAddr[mt] = AbS + ((wm * 32 + mt * 16 + (matid & 1) * 8 + lrow) * SWH
                           + (matid >> 1) * 8) * 2;
    const unsigned bAddr = WbS + ((wn * 16 + (matid >> 1) * 8 + lrow) * SWH
                                  + (matid & 1) * 8) * 2;

    // preload ALL weight fragments into registers (invariant across steps)
    unsigned breg[128];
    #pragma unroll
    for (int kk = 0; kk < 32; ++kk)
        ldsm_x4(&breg[kk * 4], bAddr + (unsigned)kk * 32);

    // epilogue mapping: thread -> (row r, 4 consecutive units q..q+3)
    const int er = tid >> 2, eq = (tid & 3) * 4;

    // prologue: prefetch X(0) into buf 0
    {
        const __half* Xbase = g_Xpre + ((size_t)0 * NB + cm * 64) * G4H;
        #pragma unroll
        for (int j = 0; j < 2; ++j) {
            int p = tid + NTHR * j;
            int r = p >> 3, g = (p >> 1) & 3, q = p & 1;
            cp16(Xb[0] + r * SXH + g * 16 + q * 8,
                 Xbase + (size_t)r * G4H + g * HID + cn * 16 + q * 8);
        }
        cp_commit();
    }

    for (int s = 0; s < L_SEQ; ++s) {
        const __half* Hsrc = &g_H[s & 1][cm * 64][0];   // [64][512] halves

        // stage H in 5 groups (64,64,128,128,128 cols) + X(s+1) (group 6)
        #pragma unroll
        for (int hg = 0; hg < 2; ++hg) {                // 64-col half-chunks
            #pragma unroll
            for (int j = 0; j < 2; ++j) {
                int p = tid + NTHR * j;                 // 0..511
                int r = p >> 3, q = p & 7;
                cp16(Ab + r * SWH + hg * 64 + q * 8, Hsrc + r * HID + hg * 64 + q * 8);
            }
            cp_commit();
        }
        #pragma unroll
        for (int c = 1; c < 4; ++c) {                   // full 128-col chunks
            #pragma unroll
            for (int j = 0; j < 4; ++j) {
                int p = tid + NTHR * j;
                int r = p >> 4, q = p & 15;
                cp16(Ab + r * SWH + c * KCH + q * 8, Hsrc + r * HID + c * KCH + q * 8);
            }
            cp_commit();
        }
        {
            int sn = (s + 1 < L_SEQ) ? s + 1 : s;
            const __half* Xbase = g_Xpre + ((size_t)sn * NB + cm * 64) * G4H;
            __half* xd = Xb[(s + 1) & 1];
            #pragma unroll
            for (int j = 0; j < 2; ++j) {
                int p = tid + NTHR * j;
                int r = p >> 3, g = (p >> 1) & 3, q = p & 1;
                cp16(xd + r * SXH + g * 16 + q * 8,
                     Xbase + (size_t)r * G4H + g * HID + cn * 16 + q * 8);
            }
            cp_commit();
        }

        float acc[2][2][4];
        #pragma unroll
        for (int mt = 0; mt < 2; ++mt)
            #pragma unroll
            for (int nt = 0; nt < 2; ++nt)
                #pragma unroll
                for (int q = 0; q < 4; ++q) acc[mt][nt][q] = 0.f;

        cp_wait<5>(); __syncthreads();
        #pragma unroll
        for (int kk = 0; kk < 4; ++kk)
            do_kk(acc, aAddr[0], aAddr[1], (unsigned)kk * 32, &breg[kk * 4]);
        cp_wait<4>(); __syncthreads();
        #pragma unroll
        for (int kk = 4; kk < 8; ++kk)
            do_kk(acc, aAddr[0], aAddr[1], (unsigned)kk * 32, &breg[kk * 4]);
        cp_wait<3>(); __syncthreads();
        #pragma unroll
        for (int kk = 8; kk < 16; ++kk)
            do_kk(acc, aAddr[0], aAddr[1], (unsigned)kk * 32, &breg[kk * 4]);
        cp_wait<2>(); __syncthreads();
        #pragma unroll
        for (int kk = 16; kk < 24; ++kk)
            do_kk(acc, aAddr[0], aAddr[1], (unsigned)kk * 32, &breg[kk * 4]);
        cp_wait<1>(); __syncthreads();
        #pragma unroll
        for (int kk = 24; kk < 32; ++kk)
            do_kk(acc, aAddr[0], aAddr[1], (unsigned)kk * 32, &breg[kk * 4]);

        // store G (64x64 f32)
        {
            const int gid = lane >> 2, tg = lane & 3;
            #pragma unroll
            for (int mt = 0; mt < 2; ++mt)
                #pragma unroll
                for (int nt = 0; nt < 2; ++nt) {
                    float* gp = Gs + (wm * 32 + mt * 16 + gid) * SG + wn * 16 + nt * 8 + tg * 2;
                    gp[0] = acc[mt][nt][0];
                    gp[1] = acc[mt][nt][1];
                    gp[8 * SG]     = acc[mt][nt][2];
                    gp[8 * SG + 1] = acc[mt][nt][3];
                }
        }
        __syncthreads();

        // epilogue: 4 consecutive units per thread, vectorized
        {
            const __half* xr = Xb[s & 1] + er * SXH;
            const float*  gp = Gs + er * SG;
            float xF[4], xI[4], xO[4], xT[4];
            ld4h(xF, xr + eq); ld4h(xI, xr + 16 + eq);
            ld4h(xO, xr + 32 + eq); ld4h(xT, xr + 48 + eq);
            float4 c4 = *(float4*)(Cs + er * 16 + eq);
            float cc[4] = {c4.x, c4.y, c4.z, c4.w};
            float h[4];
            #pragma unroll
            for (int k = 0; k < 4; ++k) {
                float gF = gp[eq + k]      + xF[k];
                float gI = gp[16 + eq + k] + xI[k];
                float gO = gp[32 + eq + k] + xO[k];
                float gT = gp[48 + eq + k] + xT[k];
                float F = sigf(gF), I = sigf(gI), O = sigf(gO);
                float T = tanhfast(gT);
                cc[k] = F * cc[k] + I * T;
                h[k] = O * tanhfast(cc[k]);
            }
            *(float4*)(Cs + er * 16 + eq) = make_float4(cc[0], cc[1], cc[2], cc[3]);
            int gr = cm * 64 + er, gc = cn * 16 + eq;
            unsigned u01 = h2_bits(__floats2half2_rn(h[0], h[1]));
            unsigned u23 = h2_bits(__floats2half2_rn(h[2], h[3]));
            __half* hp = &g_H[(s + 1) & 1][gr][gc];
            asm volatile("st.global.cg.v2.u32 [%0], {%1, %2};"
                         :: "l"(hp), "r"(u01), "r"(u23));
            if (s == L_SEQ - 1)
                *(float4*)(out + gr * HID + gc) = make_float4(h[0], h[1], h[2], h[3]);
        }

        // flag barrier over this cm-group only: release own flag, warp 0 polls all 32
        __syncthreads();
        if (tid < 32) {
            unsigned tgt = (unsigned)(s + 1);
            if (tid == cn)
                asm volatile("st.release.gpu.global.u32 [%0], %1;"
                             :: "l"(&g_flags[cm][cn][0]), "r"(tgt) : "memory");
            unsigned v;
            do {
                asm volatile("ld.acquire.gpu.global.u32 %0, [%1];"
                             : "=r"(v) : "l"(&g_flags[cm][tid][0]) : "memory");
            } while (!__all_sync(0xffffffffu, v >= tgt));
        }
        __syncthreads();
    }
}

extern "C" void kernel_launch(void* const* d_in, const int* in_sizes, int n_in,
                              void* d_out, int out_size) {
    const int*   X  = (const int*)d_in[0];
    const float* E  = (const float*)d_in[1];
    const float* Ww = (const float*)d_in[2];
    const float* Wb = (const float*)d_in[3];
    float* out = (float*)d_out;

    cudaFuncSetAttribute(lstm_xpre, cudaFuncAttributeMaxDynamicSharedMemorySize, XP_SMEM);
    cudaFuncSetAttribute(lstm_rec,  cudaFuncAttributeMaxDynamicSharedMemorySize, REC_SMEM);

    lstm_xpre<<<dim3(L_SEQ * NB / 128, G4H / 128), 256, XP_SMEM>>>(X, E, Ww, Wb);
    lstm_rec<<<NCTA, NTHR, REC_SMEM>>>(Ww, out);
}